// round 4
// baseline (speedup 1.0000x reference)
#include <cuda_runtime.h>

// ---------------------------------------------------------------------------
// Leaky CTRNN persistent scan, v2. B=64, T=512, D_IN=256, H=1024, D_OUT=256
//
//  k1: gemm_in0  — xin0[t][h][b] = W_in0 @ x[:,t,:]^T + b0
//  k2: rnn_persistent — 96 blocks x 512 thr (1/SM, co-resident), 514 phases:
//       role0 (blk  0-31): fr0(p)   = relu(v0=.9v0+.1(fr0(p-1)@Wrec0^T + xin0))
//       role1 (blk 32-63): pin(p-1) = fr0(p-1)@Win1^T + b1
//       role2 (blk 64-95): fr1(p-2) = relu(v1=.9v1+.1(fr1(p-3)@Wrec1^T + pin))
//      Weights persist in smem (32 cols/block, k-major). Block-internal
//      split-K x8 (8 slices x 64 threads), microtile 8 batch-pairs x 2 cols,
//      packed fma.rn.f32x2; partials reduced via smem. fr history written
//      coalesced to [t][h][b] buffers.
//  k3: transpose — [t][h][b] -> states[b][t][h] (both layers)
//  k4: gemm_out — output = states1 @ W_out^T + b_out
// ---------------------------------------------------------------------------

namespace {
constexpr int B = 64, T = 512, DIN = 256, H = 1024, DOUT = 256;
constexpr float AL = 0.1f, OMA = 0.9f;

constexpr int NBLK = 96;
constexpr int THR  = 512;
constexpr int NCOL = 32;             // weight cols per block
constexpr int KC   = 128;            // k-chunk staged in smem
constexpr int NCH  = H / KC;         // 8
constexpr int HB   = H * B;          // 65536
constexpr int ABUF = 2 * KC * B;     // floats (64KB)
constexpr int SMEM_P = (ABUF + H * NCOL) * 4;  // 64KB + 128KB = 192KB
}

// Scratch (__device__ globals: allocation-free rule)
__device__ float g_xin0[(size_t)T * H * B];   // [t][h][b]
__device__ float g_s0f[(size_t)T * H * B];    // fr0 history [t][h][b]
__device__ float g_s1f[(size_t)T * H * B];    // fr1 history [t][h][b]
__device__ float g_pin[2 * (size_t)H * B];    // [t&1][h][b]
__device__ volatile unsigned g_gen;
__device__ unsigned g_cnt;

// ---- helpers ---------------------------------------------------------------
__device__ __forceinline__ unsigned long long dup2(float x) {
    unsigned long long d;
    asm("mov.b64 %0, {%1, %1};" : "=l"(d) : "r"(__float_as_uint(x)));
    return d;
}
__device__ __forceinline__ void fma2(unsigned long long& a,
                                     unsigned long long x, unsigned long long y) {
    asm("fma.rn.f32x2 %0, %1, %2, %0;" : "+l"(a) : "l"(x), "l"(y));
}
__device__ __forceinline__ void cp16(float* d, const float* s) {
    unsigned a = (unsigned)__cvta_generic_to_shared(d);
    asm volatile("cp.async.cg.shared.global [%0], [%1], 16;" :: "r"(a), "l"(s));
}
#define CPCOMMIT() asm volatile("cp.async.commit_group;")
#define CPWAIT(n)  asm volatile("cp.async.wait_group %0;" :: "n"(n))

__device__ __forceinline__ void gridbar() {
    __syncthreads();
    if (threadIdx.x == 0) {
        __threadfence();
        unsigned gen = g_gen;
        if (atomicAdd(&g_cnt, 1u) == NBLK - 1) {
            g_cnt = 0;
            __threadfence();
            g_gen = gen + 1;
        } else {
            while (g_gen == gen) { __nanosleep(64); }
            __threadfence();
        }
    }
    __syncthreads();
}

// ---------------------------------------------------------------------------
__global__ void __launch_bounds__(THR, 1)
rnn_persistent(const float* __restrict__ Wrec0, const float* __restrict__ Win1,
               const float* __restrict__ Wrec1, const float* __restrict__ b1)
{
    extern __shared__ float sm[];
    float* aS = sm;                  // [2][KC][B]  (reused as reduce scratch)
    float* wS = sm + ABUF;           // [H][NCOL]   k-major

    const int tid  = threadIdx.x;
    const int role = (int)blockIdx.x >> 5;
    const int n0   = ((int)blockIdx.x & 31) * NCOL;

    // split-K slice / microtile mapping
    const int kt = tid >> 6;          // k-slice 0..7
    const int tl = tid & 63;
    const int bg = tl & 3;            // batch group: 16 batches
    const int cp = tl >> 2;           // col pair 0..15
    const int bbase = bg * 16;

    // One-time weight load: wS[k][n] = W[n0+n][k]
    const float* Wsrc = role == 0 ? Wrec0 : (role == 1 ? Win1 : Wrec1);
    for (int it = tid; it < NCOL * (H / 4); it += THR) {
        int n = it & 31, k4 = (it >> 5) << 2;
        float4 w = *(const float4*)(Wsrc + (size_t)(n0 + n) * H + k4);
        wS[(k4 + 0) * NCOL + n] = w.x; wS[(k4 + 1) * NCOL + n] = w.y;
        wS[(k4 + 2) * NCOL + n] = w.z; wS[(k4 + 3) * NCOL + n] = w.w;
    }
    // epilogue mapping: 4 contiguous outputs per thread
    const int en = tid >> 4;          // local col 0..31
    const int eb = (tid & 15) * 4;    // batch 0..60
    const float b1v = (role == 1) ? b1[n0 + en] : 0.f;
    __syncthreads();

    float v[4] = {0.f, 0.f, 0.f, 0.f};

    for (int p = 0; p < T + 2; p++) {
        int t; const float* asrc = nullptr; bool act, dogemm;
        if (role == 0) {
            t = p; act = (t < T); dogemm = act && (p > 0);
            if (dogemm) asrc = g_s0f + (size_t)(p - 1) * HB;
        } else if (role == 1) {
            t = p - 1; act = (t >= 0 && t < T); dogemm = act;
            if (dogemm) asrc = g_s0f + (size_t)t * HB;
        } else {
            t = p - 2; act = (t >= 0 && t < T); dogemm = act && (t > 0);
            if (dogemm) asrc = g_s1f + (size_t)(t - 1) * HB;
        }

        unsigned long long acc[2][8];
        #pragma unroll
        for (int c2 = 0; c2 < 2; c2++)
            #pragma unroll
            for (int j = 0; j < 8; j++) acc[c2][j] = 0ull;

        if (dogemm) {
            #pragma unroll
            for (int j = 0; j < 4; j++) {            // prefetch chunk 0
                int off = (j * THR + tid) * 4;
                cp16(aS + off, asrc + off);
            }
            CPCOMMIT();
            for (int c = 0; c < NCH; c++) {
                if (c + 1 < NCH) {
                    const float* s = asrc + (size_t)(c + 1) * KC * B;
                    float* d = aS + ((c + 1) & 1) * KC * B;
                    #pragma unroll
                    for (int j = 0; j < 4; j++) {
                        int off = (j * THR + tid) * 4;
                        cp16(d + off, s + off);
                    }
                    CPCOMMIT();
                    CPWAIT(1);
                } else {
                    CPWAIT(0);
                }
                __syncthreads();
                const float* ab = aS + (c & 1) * (KC * B) + (kt * 16) * B + bbase;
                const float* wb = wS + (c * KC + kt * 16) * NCOL + cp * 2;
                #pragma unroll
                for (int kk = 0; kk < 16; kk++) {
                    ulonglong2 A0 = *(const ulonglong2*)(ab + kk * B + 0);
                    ulonglong2 A1 = *(const ulonglong2*)(ab + kk * B + 4);
                    ulonglong2 A2 = *(const ulonglong2*)(ab + kk * B + 8);
                    ulonglong2 A3 = *(const ulonglong2*)(ab + kk * B + 12);
                    float2 w = *(const float2*)(wb + kk * NCOL);
                    unsigned long long wx = dup2(w.x), wy = dup2(w.y);
                    fma2(acc[0][0], A0.x, wx); fma2(acc[0][1], A0.y, wx);
                    fma2(acc[0][2], A1.x, wx); fma2(acc[0][3], A1.y, wx);
                    fma2(acc[0][4], A2.x, wx); fma2(acc[0][5], A2.y, wx);
                    fma2(acc[0][6], A3.x, wx); fma2(acc[0][7], A3.y, wx);
                    fma2(acc[1][0], A0.x, wy); fma2(acc[1][1], A0.y, wy);
                    fma2(acc[1][2], A1.x, wy); fma2(acc[1][3], A1.y, wy);
                    fma2(acc[1][4], A2.x, wy); fma2(acc[1][5], A2.y, wy);
                    fma2(acc[1][6], A3.x, wy); fma2(acc[1][7], A3.y, wy);
                }
                __syncthreads();
            }
        }

        if (act) {
            // write split-K partials into smem (reuse aS): red[kt][n][b]
            unsigned long long* red = (unsigned long long*)aS;
            #pragma unroll
            for (int c2 = 0; c2 < 2; c2++)
                #pragma unroll
                for (int j = 0; j < 8; j++)
                    red[kt * 1024 + (cp * 2 + c2) * 32 + bg * 8 + j] = acc[c2][j];
            __syncthreads();

            float4 s = make_float4(0.f, 0.f, 0.f, 0.f);
            #pragma unroll
            for (int q = 0; q < 8; q++) {
                float4 pz = *(const float4*)&aS[q * 2048 + en * 64 + eb];
                s.x += pz.x; s.y += pz.y; s.z += pz.z; s.w += pz.w;
            }
            const size_t vo = ((size_t)t * H + n0 + en) * B + eb;
            if (role == 1) {
                float4 o = make_float4(s.x + b1v, s.y + b1v, s.z + b1v, s.w + b1v);
                *(float4*)&g_pin[(size_t)(t & 1) * HB + (size_t)(n0 + en) * B + eb] = o;
            } else {
                float4 add;
                if (role == 0)
                    add = *(const float4*)&g_xin0[vo];
                else
                    add = __ldcg((const float4*)&g_pin[(size_t)(t & 1) * HB +
                                                       (size_t)(n0 + en) * B + eb]);
                v[0] = OMA * v[0] + AL * (s.x + add.x);
                v[1] = OMA * v[1] + AL * (s.y + add.y);
                v[2] = OMA * v[2] + AL * (s.z + add.z);
                v[3] = OMA * v[3] + AL * (s.w + add.w);
                float4 f = make_float4(fmaxf(v[0], 0.f), fmaxf(v[1], 0.f),
                                       fmaxf(v[2], 0.f), fmaxf(v[3], 0.f));
                float* dst = (role == 0) ? g_s0f : g_s1f;
                *(float4*)&dst[vo] = f;
            }
        }
        if (p < T + 1) gridbar();
    }
}

// ---------------------------------------------------------------------------
// transpose: [t][h][b] -> [b][t][h] for both layers.  grid (T, H/64, 2)
// ---------------------------------------------------------------------------
__global__ void __launch_bounds__(256)
transpose_kernel(float* __restrict__ st0, float* __restrict__ st1)
{
    __shared__ float tile[64][65];
    const int t  = blockIdx.x;
    const int h0 = blockIdx.y * 64;
    const float* src = blockIdx.z ? g_s1f : g_s0f;
    float* dst       = blockIdx.z ? st1 : st0;
    const int tid = threadIdx.x;
    #pragma unroll
    for (int i = tid; i < 64 * 64; i += 256) {
        int h = i >> 6, b = i & 63;
        tile[h][b] = src[((size_t)t * H + h0 + h) * B + b];
    }
    __syncthreads();
    #pragma unroll
    for (int i = tid; i < 64 * 64; i += 256) {
        int b = i >> 6, h = i & 63;
        dst[((size_t)b * T + t) * H + h0 + h] = tile[h][b];
    }
}

// ---------------------------------------------------------------------------
// gemm_in0: per timestep t, xin0[t][h][b] = W_in0[h,:] . x[b,t,:] + b0[h]
// ---------------------------------------------------------------------------
__global__ void __launch_bounds__(256)
gemm_in0_kernel(const float* __restrict__ x,
                const float* __restrict__ Win0,
                const float* __restrict__ b0)
{
    __shared__ float aS[16 * 64];
    __shared__ float bS[16 * 64];
    const int tid = threadIdx.x;
    const int m0 = blockIdx.x * 64;
    const int t  = blockIdx.y;
    const int lr = tid >> 2;
    const int lk = (tid & 3) * 4;
    const int tm4 = (tid >> 4) * 4;
    const int tn4 = (tid & 15) * 4;
    float acc[4][4] = {};
    const float* ap = Win0 + (size_t)(m0 + lr) * DIN + lk;
    const float* bp = x + ((size_t)lr * T + t) * DIN + lk;

    for (int k0 = 0; k0 < DIN; k0 += 16) {
        float4 av = *(const float4*)(ap + k0);
        float4 bv = *(const float4*)(bp + k0);
        __syncthreads();
        aS[(lk + 0) * 64 + lr] = av.x; aS[(lk + 1) * 64 + lr] = av.y;
        aS[(lk + 2) * 64 + lr] = av.z; aS[(lk + 3) * 64 + lr] = av.w;
        bS[(lk + 0) * 64 + lr] = bv.x; bS[(lk + 1) * 64 + lr] = bv.y;
        bS[(lk + 2) * 64 + lr] = bv.z; bS[(lk + 3) * 64 + lr] = bv.w;
        __syncthreads();
        #pragma unroll
        for (int kk = 0; kk < 16; kk++) {
            float4 a = *(const float4*)&aS[kk * 64 + tm4];
            float4 b = *(const float4*)&bS[kk * 64 + tn4];
            acc[0][0] += a.x * b.x; acc[0][1] += a.x * b.y;
            acc[0][2] += a.x * b.z; acc[0][3] += a.x * b.w;
            acc[1][0] += a.y * b.x; acc[1][1] += a.y * b.y;
            acc[1][2] += a.y * b.z; acc[1][3] += a.y * b.w;
            acc[2][0] += a.z * b.x; acc[2][1] += a.z * b.y;
            acc[2][2] += a.z * b.z; acc[2][3] += a.z * b.w;
            acc[3][0] += a.w * b.x; acc[3][1] += a.w * b.y;
            acc[3][2] += a.w * b.z; acc[3][3] += a.w * b.w;
        }
    }
    #pragma unroll
    for (int i = 0; i < 4; i++) {
        float bb = b0[m0 + tm4 + i];
        float4 o = make_float4(acc[i][0] + bb, acc[i][1] + bb,
                               acc[i][2] + bb, acc[i][3] + bb);
        *(float4*)&g_xin0[((size_t)t * H + m0 + tm4 + i) * B + tn4] = o;
    }
}

// ---------------------------------------------------------------------------
// gemm_out: output[B*T, DOUT] = states1[B*T, H] @ W_out^T + b_out
// ---------------------------------------------------------------------------
__global__ void __launch_bounds__(256)
gemm_out_kernel(const float* __restrict__ states1,
                const float* __restrict__ Wout,
                const float* __restrict__ bout,
                float* __restrict__ out)
{
    __shared__ float aS[16 * 64];
    __shared__ float bS[16 * 64];
    const int tid = threadIdx.x;
    const int m0 = blockIdx.x * 64;
    const int n0 = blockIdx.y * 64;
    const int lr = tid >> 2;
    const int lk = (tid & 3) * 4;
    const int tm4 = (tid >> 4) * 4;
    const int tn4 = (tid & 15) * 4;
    float acc[4][4] = {};
    const float* ap = states1 + (size_t)(m0 + lr) * H + lk;
    const float* bp = Wout    + (size_t)(n0 + lr) * H + lk;

    for (int k0 = 0; k0 < H; k0 += 16) {
        float4 av = *(const float4*)(ap + k0);
        float4 bv = *(const float4*)(bp + k0);
        __syncthreads();
        aS[(lk + 0) * 64 + lr] = av.x; aS[(lk + 1) * 64 + lr] = av.y;
        aS[(lk + 2) * 64 + lr] = av.z; aS[(lk + 3) * 64 + lr] = av.w;
        bS[(lk + 0) * 64 + lr] = bv.x; bS[(lk + 1) * 64 + lr] = bv.y;
        bS[(lk + 2) * 64 + lr] = bv.z; bS[(lk + 3) * 64 + lr] = bv.w;
        __syncthreads();
        #pragma unroll
        for (int kk = 0; kk < 16; kk++) {
            float4 a = *(const float4*)&aS[kk * 64 + tm4];
            float4 b = *(const float4*)&bS[kk * 64 + tn4];
            acc[0][0] += a.x * b.x; acc[0][1] += a.x * b.y;
            acc[0][2] += a.x * b.z; acc[0][3] += a.x * b.w;
            acc[1][0] += a.y * b.x; acc[1][1] += a.y * b.y;
            acc[1][2] += a.y * b.z; acc[1][3] += a.y * b.w;
            acc[2][0] += a.z * b.x; acc[2][1] += a.z * b.y;
            acc[2][2] += a.z * b.z; acc[2][3] += a.z * b.w;
            acc[3][0] += a.w * b.x; acc[3][1] += a.w * b.y;
            acc[3][2] += a.w * b.z; acc[3][3] += a.w * b.w;
        }
    }
    #pragma unroll
    for (int i = 0; i < 4; i++) {
        float4 bb = *(const float4*)&bout[n0 + tn4];
        int gm = m0 + tm4 + i;
        float4 o = make_float4(acc[i][0] + bb.x, acc[i][1] + bb.y,
                               acc[i][2] + bb.z, acc[i][3] + bb.w);
        *(float4*)&out[(size_t)gm * DOUT + n0 + tn4] = o;
    }
}

// ---------------------------------------------------------------------------
extern "C" void kernel_launch(void* const* d_in, const int* in_sizes, int n_in,
                              void* d_out, int out_size)
{
    (void)in_sizes; (void)n_in; (void)out_size;
    const float* x     = (const float*)d_in[0];
    const float* Win0  = (const float*)d_in[1];
    const float* Wrec0 = (const float*)d_in[2];
    const float* b0    = (const float*)d_in[3];
    const float* Win1  = (const float*)d_in[4];
    const float* Wrec1 = (const float*)d_in[5];
    const float* b1    = (const float*)d_in[6];
    const float* Wout  = (const float*)d_in[7];
    const float* bout  = (const float*)d_in[8];

    float* out     = (float*)d_out;                   // [B][T][DOUT]
    float* states0 = out + (size_t)B * T * DOUT;      // [B][T][H]
    float* states1 = states0 + (size_t)B * T * H;     // [B][T][H]

    cudaFuncSetAttribute(rnn_persistent,
                         cudaFuncAttributeMaxDynamicSharedMemorySize, SMEM_P);

    gemm_in0_kernel<<<dim3(H / 64, T), 256>>>(x, Win0, b0);
    rnn_persistent<<<NBLK, THR, SMEM_P>>>(Wrec0, Win1, Wrec1, b1);
    transpose_kernel<<<dim3(T, H / 64, 2), 256>>>(states0, states1);
    gemm_out_kernel<<<dim3((B * T) / 64, DOUT / 64), 256>>>(states1, Wout,
                                                            bout, out);
}

// round 5
// speedup vs baseline: 1.6086x; 1.6086x over previous
#include <cuda_runtime.h>

// ---------------------------------------------------------------------------
// Leaky CTRNN persistent scan, v3. B=64, T=512, D_IN=256, H=1024, D_OUT=256
//
//  k1: gemm_in0 — xin0[t][h][b] = W_in0 @ x[:,t,:]^T + b0
//  k2: rnn_persistent — 96 blocks x 512 thr (1/SM, co-resident), 514 phases:
//       role0 (blk  0-31): fr0(p)   = relu(v0=.9v0+.1(fr0(p-1)@Wrec0^T + xin0))
//       role1 (blk 32-63): pin(p-1) = fr0(p-1)@Win1^T + b1
//       role2 (blk 64-95): fr1(p-2) = relu(v1=.9v1+.1(fr1(p-3)@Wrec1^T + pin))
//      Weights persist in smem (32 cols/block, k-major). Split-K x8
//      interleaved per 128-k chunk; microtile 8 batches x 4 cols / thread;
//      packed fma.rn.f32x2; conflict-free LDS; one smem reduce per phase.
//  k3: transpose — [t][h][b] -> states[b][t][h]
//  k4: gemm_out — output = states1 @ W_out^T + b_out
// ---------------------------------------------------------------------------

namespace {
constexpr int B = 64, T = 512, DIN = 256, H = 1024, DOUT = 256;
constexpr float AL = 0.1f, OMA = 0.9f;

constexpr int NBLK = 96;
constexpr int THR  = 512;
constexpr int NCOL = 32;             // weight cols per block
constexpr int KC   = 128;            // k-chunk staged in smem
constexpr int NCH  = H / KC;         // 8
constexpr int HB   = H * B;
constexpr int ABUF = 2 * KC * B;     // floats (64KB), reused for reduce
constexpr int SMEM_P = (ABUF + H * NCOL) * 4;   // 64KB + 128KB = 192KB
}

// Scratch (__device__ globals: allocation-free rule)
__device__ float g_xin0[(size_t)T * H * B];   // [t][h][b]
__device__ float g_s0f[(size_t)T * H * B];    // fr0 history [t][h][b]
__device__ float g_s1f[(size_t)T * H * B];    // fr1 history [t][h][b]
__device__ float g_pin[2 * (size_t)H * B];    // [t&1][h][b]
__device__ volatile unsigned g_gen;
__device__ unsigned g_cnt;

// ---- helpers ---------------------------------------------------------------
__device__ __forceinline__ unsigned long long dup2(float x) {
    unsigned long long d;
    asm("mov.b64 %0, {%1, %1};" : "=l"(d) : "r"(__float_as_uint(x)));
    return d;
}
__device__ __forceinline__ void fma2(unsigned long long& a,
                                     unsigned long long x, unsigned long long y) {
    asm("fma.rn.f32x2 %0, %1, %2, %0;" : "+l"(a) : "l"(x), "l"(y));
}
__device__ __forceinline__ void cp16(float* d, const float* s) {
    unsigned a = (unsigned)__cvta_generic_to_shared(d);
    asm volatile("cp.async.cg.shared.global [%0], [%1], 16;" :: "r"(a), "l"(s));
}
#define CPCOMMIT() asm volatile("cp.async.commit_group;")
#define CPWAIT(n)  asm volatile("cp.async.wait_group %0;" :: "n"(n))

__device__ __forceinline__ void gridbar() {
    __syncthreads();
    if (threadIdx.x == 0) {
        __threadfence();
        unsigned gen = g_gen;
        if (atomicAdd(&g_cnt, 1u) == NBLK - 1) {
            g_cnt = 0;
            __threadfence();
            g_gen = gen + 1;
        } else {
            while (g_gen == gen) { __nanosleep(64); }
            __threadfence();
        }
    }
    __syncthreads();
}

// ---------------------------------------------------------------------------
__global__ void __launch_bounds__(THR, 1)
rnn_persistent(const float* __restrict__ Wrec0, const float* __restrict__ Win1,
               const float* __restrict__ Wrec1, const float* __restrict__ b1)
{
    extern __shared__ float sm[];
    float* aS = sm;                  // [2][KC][B], reused as reduce scratch
    float* wS = sm + ABUF;           // [H][NCOL] k-major

    const int tid  = threadIdx.x;
    const int role = (int)blockIdx.x >> 5;
    const int n0   = ((int)blockIdx.x & 31) * NCOL;

    // split-K slice / microtile mapping (conflict-free LDS)
    const int kt     = tid >> 6;         // k-slice 0..7
    const int tl     = tid & 63;
    const int bgroup = tl & 7;           // 8 batches each -> bbase = bgroup*8
    const int cgroup = tl >> 3;          // 4 cols each    -> cbase = cgroup*4
    const int bbase  = bgroup * 8;
    const int cbase  = cgroup * 4;

    // One-time weight load: wS[k][n] = W[n0+n][k]
    const float* Wsrc = role == 0 ? Wrec0 : (role == 1 ? Win1 : Wrec1);
    for (int it = tid; it < NCOL * (H / 4); it += THR) {
        int n = it & 31, k4 = (it >> 5) << 2;
        float4 w = *(const float4*)(Wsrc + (size_t)(n0 + n) * H + k4);
        wS[(k4 + 0) * NCOL + n] = w.x; wS[(k4 + 1) * NCOL + n] = w.y;
        wS[(k4 + 2) * NCOL + n] = w.z; wS[(k4 + 3) * NCOL + n] = w.w;
    }
    // epilogue mapping: 4 contiguous batch outputs of one col per thread
    const int en = tid >> 4;             // local col 0..31
    const int eb = (tid & 15) * 4;       // batch 0..60
    const float b1v = (role == 1) ? b1[n0 + en] : 0.f;
    __syncthreads();

    float v[4] = {0.f, 0.f, 0.f, 0.f};

    for (int p = 0; p < T + 2; p++) {
        int t; const float* asrc = nullptr; bool act, dogemm;
        if (role == 0) {
            t = p; act = (t < T); dogemm = act && (p > 0);
            if (dogemm) asrc = g_s0f + (size_t)(p - 1) * HB;
        } else if (role == 1) {
            t = p - 1; act = (t >= 0 && t < T); dogemm = act;
            if (dogemm) asrc = g_s0f + (size_t)t * HB;
        } else {
            t = p - 2; act = (t >= 0 && t < T); dogemm = act && (t > 0);
            if (dogemm) asrc = g_s1f + (size_t)(t - 1) * HB;
        }

        // acc[col 0..3][batch-pair 0..3]
        unsigned long long acc[4][4];
        #pragma unroll
        for (int c2 = 0; c2 < 4; c2++)
            #pragma unroll
            for (int j = 0; j < 4; j++) acc[c2][j] = 0ull;

        if (dogemm) {
            #pragma unroll
            for (int j = 0; j < 4; j++) {            // prefetch chunk 0
                int off = (j * THR + tid) * 4;
                cp16(aS + off, asrc + off);
            }
            CPCOMMIT();
            for (int c = 0; c < NCH; c++) {
                if (c + 1 < NCH) {
                    const float* s = asrc + (size_t)(c + 1) * KC * B;
                    float* d = aS + ((c + 1) & 1) * KC * B;
                    #pragma unroll
                    for (int j = 0; j < 4; j++) {
                        int off = (j * THR + tid) * 4;
                        cp16(d + off, s + off);
                    }
                    CPCOMMIT();
                    CPWAIT(1);
                } else {
                    CPWAIT(0);
                }
                __syncthreads();
                const float* ab = aS + (c & 1) * (KC * B) + (kt * 16) * B + bbase;
                const float* wb = wS + (c * KC + kt * 16) * NCOL + cbase;
                #pragma unroll
                for (int kk = 0; kk < 16; kk++) {
                    ulonglong2 A0 = *(const ulonglong2*)(ab + kk * B);      // b..b+3
                    ulonglong2 A1 = *(const ulonglong2*)(ab + kk * B + 4);  // b+4..b+7
                    float4 w = *(const float4*)(wb + kk * NCOL);
                    unsigned long long w0 = dup2(w.x), w1 = dup2(w.y);
                    unsigned long long w2 = dup2(w.z), w3 = dup2(w.w);
                    fma2(acc[0][0], A0.x, w0); fma2(acc[0][1], A0.y, w0);
                    fma2(acc[0][2], A1.x, w0); fma2(acc[0][3], A1.y, w0);
                    fma2(acc[1][0], A0.x, w1); fma2(acc[1][1], A0.y, w1);
                    fma2(acc[1][2], A1.x, w1); fma2(acc[1][3], A1.y, w1);
                    fma2(acc[2][0], A0.x, w2); fma2(acc[2][1], A0.y, w2);
                    fma2(acc[2][2], A1.x, w2); fma2(acc[2][3], A1.y, w2);
                    fma2(acc[3][0], A0.x, w3); fma2(acc[3][1], A0.y, w3);
                    fma2(acc[3][2], A1.x, w3); fma2(acc[3][3], A1.y, w3);
                }
                __syncthreads();
            }
        }

        if (act) {
            // split-K partials -> smem: red[kt][n][b] (ull = batch pair)
            unsigned long long* red = (unsigned long long*)aS;
            #pragma unroll
            for (int c2 = 0; c2 < 4; c2++)
                #pragma unroll
                for (int j = 0; j < 4; j++)
                    red[kt * 1024 + (cbase + c2) * 32 + bgroup * 4 + j] = acc[c2][j];
            __syncthreads();

            float4 s = make_float4(0.f, 0.f, 0.f, 0.f);
            #pragma unroll
            for (int q = 0; q < 8; q++) {
                float4 pz = *(const float4*)&aS[q * 2048 + en * 64 + eb];
                s.x += pz.x; s.y += pz.y; s.z += pz.z; s.w += pz.w;
            }
            const size_t vo = ((size_t)t * H + n0 + en) * B + eb;
            if (role == 1) {
                float4 o = make_float4(s.x + b1v, s.y + b1v, s.z + b1v, s.w + b1v);
                *(float4*)&g_pin[(size_t)(t & 1) * HB + (size_t)(n0 + en) * B + eb] = o;
            } else {
                float4 add;
                if (role == 0)
                    add = *(const float4*)&g_xin0[vo];
                else
                    add = __ldcg((const float4*)&g_pin[(size_t)(t & 1) * HB +
                                                       (size_t)(n0 + en) * B + eb]);
                v[0] = OMA * v[0] + AL * (s.x + add.x);
                v[1] = OMA * v[1] + AL * (s.y + add.y);
                v[2] = OMA * v[2] + AL * (s.z + add.z);
                v[3] = OMA * v[3] + AL * (s.w + add.w);
                float4 f = make_float4(fmaxf(v[0], 0.f), fmaxf(v[1], 0.f),
                                       fmaxf(v[2], 0.f), fmaxf(v[3], 0.f));
                float* dst = (role == 0) ? g_s0f : g_s1f;
                *(float4*)&dst[vo] = f;
            }
        }
        if (p < T + 1) gridbar();
    }
}

// ---------------------------------------------------------------------------
// transpose: [t][h][b] -> [b][t][h] for both layers.  grid (T, H/64, 2)
// ---------------------------------------------------------------------------
__global__ void __launch_bounds__(256)
transpose_kernel(float* __restrict__ st0, float* __restrict__ st1)
{
    __shared__ float tile[64][65];
    const int t  = blockIdx.x;
    const int h0 = blockIdx.y * 64;
    const float* src = blockIdx.z ? g_s1f : g_s0f;
    float* dst       = blockIdx.z ? st1 : st0;
    const int tid = threadIdx.x;
    #pragma unroll
    for (int i = tid; i < 64 * 64; i += 256) {
        int h = i >> 6, b = i & 63;
        tile[h][b] = src[((size_t)t * H + h0 + h) * B + b];
    }
    __syncthreads();
    #pragma unroll
    for (int i = tid; i < 64 * 64; i += 256) {
        int b = i >> 6, h = i & 63;
        dst[((size_t)b * T + t) * H + h0 + h] = tile[h][b];
    }
}

// ---------------------------------------------------------------------------
// gemm_in0: per timestep t, xin0[t][h][b] = W_in0[h,:] . x[b,t,:] + b0[h]
// ---------------------------------------------------------------------------
__global__ void __launch_bounds__(256)
gemm_in0_kernel(const float* __restrict__ x,
                const float* __restrict__ Win0,
                const float* __restrict__ b0)
{
    __shared__ float aS[16 * 64];
    __shared__ float bS[16 * 64];
    const int tid = threadIdx.x;
    const int m0 = blockIdx.x * 64;
    const int t  = blockIdx.y;
    const int lr = tid >> 2;
    const int lk = (tid & 3) * 4;
    const int tm4 = (tid >> 4) * 4;
    const int tn4 = (tid & 15) * 4;
    float acc[4][4] = {};
    const float* ap = Win0 + (size_t)(m0 + lr) * DIN + lk;
    const float* bp = x + ((size_t)lr * T + t) * DIN + lk;

    for (int k0 = 0; k0 < DIN; k0 += 16) {
        float4 av = *(const float4*)(ap + k0);
        float4 bv = *(const float4*)(bp + k0);
        __syncthreads();
        aS[(lk + 0) * 64 + lr] = av.x; aS[(lk + 1) * 64 + lr] = av.y;
        aS[(lk + 2) * 64 + lr] = av.z; aS[(lk + 3) * 64 + lr] = av.w;
        bS[(lk + 0) * 64 + lr] = bv.x; bS[(lk + 1) * 64 + lr] = bv.y;
        bS[(lk + 2) * 64 + lr] = bv.z; bS[(lk + 3) * 64 + lr] = bv.w;
        __syncthreads();
        #pragma unroll
        for (int kk = 0; kk < 16; kk++) {
            float4 a = *(const float4*)&aS[kk * 64 + tm4];
            float4 b = *(const float4*)&bS[kk * 64 + tn4];
            acc[0][0] += a.x * b.x; acc[0][1] += a.x * b.y;
            acc[0][2] += a.x * b.z; acc[0][3] += a.x * b.w;
            acc[1][0] += a.y * b.x; acc[1][1] += a.y * b.y;
            acc[1][2] += a.y * b.z; acc[1][3] += a.y * b.w;
            acc[2][0] += a.z * b.x; acc[2][1] += a.z * b.y;
            acc[2][2] += a.z * b.z; acc[2][3] += a.z * b.w;
            acc[3][0] += a.w * b.x; acc[3][1] += a.w * b.y;
            acc[3][2] += a.w * b.z; acc[3][3] += a.w * b.w;
        }
    }
    #pragma unroll
    for (int i = 0; i < 4; i++) {
        float bb = b0[m0 + tm4 + i];
        float4 o = make_float4(acc[i][0] + bb, acc[i][1] + bb,
                               acc[i][2] + bb, acc[i][3] + bb);
        *(float4*)&g_xin0[((size_t)t * H + m0 + tm4 + i) * B + tn4] = o;
    }
}

// ---------------------------------------------------------------------------
// gemm_out: output[B*T, DOUT] = states1[B*T, H] @ W_out^T + b_out
// ---------------------------------------------------------------------------
__global__ void __launch_bounds__(256)
gemm_out_kernel(const float* __restrict__ states1,
                const float* __restrict__ Wout,
                const float* __restrict__ bout,
                float* __restrict__ out)
{
    __shared__ float aS[16 * 64];
    __shared__ float bS[16 * 64];
    const int tid = threadIdx.x;
    const int m0 = blockIdx.x * 64;
    const int n0 = blockIdx.y * 64;
    const int lr = tid >> 2;
    const int lk = (tid & 3) * 4;
    const int tm4 = (tid >> 4) * 4;
    const int tn4 = (tid & 15) * 4;
    float acc[4][4] = {};
    const float* ap = states1 + (size_t)(m0 + lr) * H + lk;
    const float* bp = Wout    + (size_t)(n0 + lr) * H + lk;

    for (int k0 = 0; k0 < H; k0 += 16) {
        float4 av = *(const float4*)(ap + k0);
        float4 bv = *(const float4*)(bp + k0);
        __syncthreads();
        aS[(lk + 0) * 64 + lr] = av.x; aS[(lk + 1) * 64 + lr] = av.y;
        aS[(lk + 2) * 64 + lr] = av.z; aS[(lk + 3) * 64 + lr] = av.w;
        bS[(lk + 0) * 64 + lr] = bv.x; bS[(lk + 1) * 64 + lr] = bv.y;
        bS[(lk + 2) * 64 + lr] = bv.z; bS[(lk + 3) * 64 + lr] = bv.w;
        __syncthreads();
        #pragma unroll
        for (int kk = 0; kk < 16; kk++) {
            float4 a = *(const float4*)&aS[kk * 64 + tm4];
            float4 b = *(const float4*)&bS[kk * 64 + tn4];
            acc[0][0] += a.x * b.x; acc[0][1] += a.x * b.y;
            acc[0][2] += a.x * b.z; acc[0][3] += a.x * b.w;
            acc[1][0] += a.y * b.x; acc[1][1] += a.y * b.y;
            acc[1][2] += a.y * b.z; acc[1][3] += a.y * b.w;
            acc[2][0] += a.z * b.x; acc[2][1] += a.z * b.y;
            acc[2][2] += a.z * b.z; acc[2][3] += a.z * b.w;
            acc[3][0] += a.w * b.x; acc[3][1] += a.w * b.y;
            acc[3][2] += a.w * b.z; acc[3][3] += a.w * b.w;
        }
    }
    #pragma unroll
    for (int i = 0; i < 4; i++) {
        float4 bb = *(const float4*)&bout[n0 + tn4];
        int gm = m0 + tm4 + i;
        float4 o = make_float4(acc[i][0] + bb.x, acc[i][1] + bb.y,
                               acc[i][2] + bb.z, acc[i][3] + bb.w);
        *(float4*)&out[(size_t)gm * DOUT + n0 + tn4] = o;
    }
}

// ---------------------------------------------------------------------------
extern "C" void kernel_launch(void* const* d_in, const int* in_sizes, int n_in,
                              void* d_out, int out_size)
{
    (void)in_sizes; (void)n_in; (void)out_size;
    const float* x     = (const float*)d_in[0];
    const float* Win0  = (const float*)d_in[1];
    const float* Wrec0 = (const float*)d_in[2];
    const float* b0    = (const float*)d_in[3];
    const float* Win1  = (const float*)d_in[4];
    const float* Wrec1 = (const float*)d_in[5];
    const float* b1    = (const float*)d_in[6];
    const float* Wout  = (const float*)d_in[7];
    const float* bout  = (const float*)d_in[8];

    float* out     = (float*)d_out;                   // [B][T][DOUT]
    float* states0 = out + (size_t)B * T * DOUT;      // [B][T][H]
    float* states1 = states0 + (size_t)B * T * H;     // [B][T][H]

    cudaFuncSetAttribute(rnn_persistent,
                         cudaFuncAttributeMaxDynamicSharedMemorySize, SMEM_P);

    gemm_in0_kernel<<<dim3(H / 64, T), 256>>>(x, Win0, b0);
    rnn_persistent<<<NBLK, THR, SMEM_P>>>(Wrec0, Win1, Wrec1, b1);
    transpose_kernel<<<dim3(T, H / 64, 2), 256>>>(states0, states1);
    gemm_out_kernel<<<dim3((B * T) / 64, DOUT / 64), 256>>>(states1, Wout,
                                                            bout, out);
}

// round 6
// speedup vs baseline: 1.6257x; 1.0106x over previous
#include <cuda_runtime.h>

// ---------------------------------------------------------------------------
// Leaky CTRNN persistent scan, v4. B=64, T=512, D_IN=256, H=1024, D_OUT=256
//
//  k1: gemm_in0 — xin0[t][h][b] = W_in0 @ x[:,t,:]^T + b0
//  k2: rnn_persistent — 96 blocks x 512 thr (1/SM, co-resident), 514 phases:
//       role0 (blk  0-31): fr0(p)   = relu(v0=.9v0+.1(fr0(p-1)@Wrec0^T + xin0))
//       role1 (blk 32-63): pin(p-1) = fr0(p-1)@Win1^T + b1
//       role2 (blk 64-95): fr1(p-2) = relu(v1=.9v1+.1(fr1(p-3)@Wrec1^T + pin))
//      Weights persist in smem. A staged per 128-k chunk via cp.async.bulk
//      (TMA) + mbarrier, double-buffered (no per-thread LDGSTS cost).
//      Split-K x8, microtile 8 batches x 4 cols / thread, fma.rn.f32x2.
//      Swizzled smem reduce (2-way STS instead of 8-way).
//  k3: transpose — [t][h][b] -> states[b][t][h]
//  k4: gemm_out — output = states1 @ W_out^T + b_out
// ---------------------------------------------------------------------------

namespace {
constexpr int B = 64, T = 512, DIN = 256, H = 1024, DOUT = 256;
constexpr float AL = 0.1f, OMA = 0.9f;

constexpr int NBLK = 96;
constexpr int THR  = 512;
constexpr int NCOL = 32;             // weight cols per block
constexpr int KC   = 128;            // k-chunk staged in smem
constexpr int NCH  = H / KC;         // 8
constexpr int HB   = H * B;
constexpr int ABUF = 2 * KC * B;     // floats (64KB), reused for reduce
constexpr int CBYTES = KC * B * 4;   // 32768 bytes per chunk
constexpr int MBAR_OFF = (ABUF + H * NCOL) * 4;     // byte offset of mbarriers
constexpr int SMEM_P   = MBAR_OFF + 16;             // + two 8B mbarriers
}

// Scratch (__device__ globals: allocation-free rule)
__device__ float g_xin0[(size_t)T * H * B];   // [t][h][b]
__device__ float g_s0f[(size_t)T * H * B];    // fr0 history [t][h][b]
__device__ float g_s1f[(size_t)T * H * B];    // fr1 history [t][h][b]
__device__ float g_pin[2 * (size_t)H * B];    // [t&1][h][b]
__device__ volatile unsigned g_gen;
__device__ unsigned g_cnt;

// ---- helpers ---------------------------------------------------------------
__device__ __forceinline__ unsigned long long dup2(float x) {
    unsigned long long d;
    asm("mov.b64 %0, {%1, %1};" : "=l"(d) : "r"(__float_as_uint(x)));
    return d;
}
__device__ __forceinline__ void fma2(unsigned long long& a,
                                     unsigned long long x, unsigned long long y) {
    asm("fma.rn.f32x2 %0, %1, %2, %0;" : "+l"(a) : "l"(x), "l"(y));
}
__device__ __forceinline__ void mbar_init(unsigned mbar, unsigned count) {
    asm volatile("mbarrier.init.shared.b64 [%0], %1;" :: "r"(mbar), "r"(count)
                 : "memory");
}
__device__ __forceinline__ void mbar_expect_tx(unsigned mbar, unsigned bytes) {
    asm volatile("mbarrier.arrive.expect_tx.shared.b64 _, [%0], %1;"
                 :: "r"(mbar), "r"(bytes) : "memory");
}
__device__ __forceinline__ void bulk_g2s(unsigned dst, const float* src,
                                         unsigned bytes, unsigned mbar) {
    asm volatile(
        "cp.async.bulk.shared::cta.global.mbarrier::complete_tx::bytes "
        "[%0], [%1], %2, [%3];"
        :: "r"(dst), "l"(src), "r"(bytes), "r"(mbar) : "memory");
}
__device__ __forceinline__ void mbar_wait(unsigned mbar, unsigned parity) {
    asm volatile(
        "{\n\t"
        ".reg .pred P;\n\t"
        "LAB_%=:\n\t"
        "mbarrier.try_wait.parity.shared.b64 P, [%0], %1;\n\t"
        "@!P bra LAB_%=;\n\t"
        "}\n"
        :: "r"(mbar), "r"(parity) : "memory");
}

__device__ __forceinline__ void gridbar() {
    __syncthreads();
    if (threadIdx.x == 0) {
        __threadfence();
        unsigned gen = g_gen;
        if (atomicAdd(&g_cnt, 1u) == NBLK - 1) {
            g_cnt = 0;
            __threadfence();
            g_gen = gen + 1;
        } else {
            while (g_gen == gen) { __nanosleep(64); }
            __threadfence();
        }
    }
    __syncthreads();
}

// ---------------------------------------------------------------------------
__global__ void __launch_bounds__(THR, 1)
rnn_persistent(const float* __restrict__ Wrec0, const float* __restrict__ Win1,
               const float* __restrict__ Wrec1, const float* __restrict__ b1)
{
    extern __shared__ float sm[];
    float* aS = sm;                  // [2][KC][B], reused as reduce scratch
    float* wS = sm + ABUF;           // [H][NCOL] k-major

    const unsigned sbase = (unsigned)__cvta_generic_to_shared(sm);
    const unsigned mb0 = sbase + MBAR_OFF;
    const unsigned mb1 = sbase + MBAR_OFF + 8;
    const unsigned abuf0 = sbase;
    const unsigned abuf1 = sbase + CBYTES;

    const int tid  = threadIdx.x;
    const int role = (int)blockIdx.x >> 5;
    const int n0   = ((int)blockIdx.x & 31) * NCOL;

    // split-K slice / microtile mapping (conflict-free LDS)
    const int kt     = tid >> 6;         // k-slice 0..7
    const int tl     = tid & 63;
    const int bgroup = tl & 7;           // 8 batches -> bbase = bgroup*8
    const int cgroup = tl >> 3;          // 4 cols    -> cbase = cgroup*4
    const int bbase  = bgroup * 8;
    const int cbase  = cgroup * 4;
    const int wkey   = cgroup & 3;       // reduce swizzle key (= (n>>2)&3)

    // One-time weight load: wS[k][n] = W[n0+n][k]
    const float* Wsrc = role == 0 ? Wrec0 : (role == 1 ? Win1 : Wrec1);
    for (int it = tid; it < NCOL * (H / 4); it += THR) {
        int n = it & 31, k4 = (it >> 5) << 2;
        float4 w = *(const float4*)(Wsrc + (size_t)(n0 + n) * H + k4);
        wS[(k4 + 0) * NCOL + n] = w.x; wS[(k4 + 1) * NCOL + n] = w.y;
        wS[(k4 + 2) * NCOL + n] = w.z; wS[(k4 + 3) * NCOL + n] = w.w;
    }
    // epilogue mapping: 4 contiguous batch outputs of one col per thread
    const int en = tid >> 4;             // local col 0..31
    const int eb = (tid & 15) * 4;       // batch 0..60
    const int ckey = (en >> 2) & 3;      // reader swizzle key
    const int prbase = (tid & 15) * 2;   // batch-pair base (even)
    const int fidx = ((prbase ^ ckey) & ~1) * 2;  // float idx of float4 slot
    const float b1v = (role == 1) ? b1[n0 + en] : 0.f;

    if (tid == 0) { mbar_init(mb0, 1); mbar_init(mb1, 1); }
    asm volatile("fence.proxy.async.shared::cta;" ::: "memory");
    __syncthreads();

    unsigned par0 = 0, par1 = 0;
    float v[4] = {0.f, 0.f, 0.f, 0.f};

    for (int p = 0; p < T + 2; p++) {
        int t; const float* asrc = nullptr; bool act, dogemm;
        if (role == 0) {
            t = p; act = (t < T); dogemm = act && (p > 0);
            if (dogemm) asrc = g_s0f + (size_t)(p - 1) * HB;
        } else if (role == 1) {
            t = p - 1; act = (t >= 0 && t < T); dogemm = act;
            if (dogemm) asrc = g_s0f + (size_t)t * HB;
        } else {
            t = p - 2; act = (t >= 0 && t < T); dogemm = act && (t > 0);
            if (dogemm) asrc = g_s1f + (size_t)(t - 1) * HB;
        }

        // acc[col 0..3][batch-pair 0..3]
        unsigned long long acc[4][4];
        #pragma unroll
        for (int c2 = 0; c2 < 4; c2++)
            #pragma unroll
            for (int j = 0; j < 4; j++) acc[c2][j] = 0ull;

        if (dogemm) {
            if (tid == 0) {                       // prefetch chunk 0
                mbar_expect_tx(mb0, CBYTES);
                bulk_g2s(abuf0, asrc, CBYTES, mb0);
            }
            for (int c = 0; c < NCH; c++) {
                if (c + 1 < NCH && tid == 0) {    // prefetch chunk c+1
                    unsigned dst = ((c + 1) & 1) ? abuf1 : abuf0;
                    unsigned mbn = ((c + 1) & 1) ? mb1 : mb0;
                    mbar_expect_tx(mbn, CBYTES);
                    bulk_g2s(dst, asrc + (size_t)(c + 1) * KC * B, CBYTES, mbn);
                }
                if (c & 1) { mbar_wait(mb1, par1); par1 ^= 1; }
                else       { mbar_wait(mb0, par0); par0 ^= 1; }

                const float* ab = aS + (c & 1) * (KC * B) + (kt * 16) * B + bbase;
                const float* wb = wS + (c * KC + kt * 16) * NCOL + cbase;
                #pragma unroll
                for (int kk = 0; kk < 16; kk++) {
                    ulonglong2 A0 = *(const ulonglong2*)(ab + kk * B);      // b..b+3
                    ulonglong2 A1 = *(const ulonglong2*)(ab + kk * B + 4);  // b+4..b+7
                    float4 w = *(const float4*)(wb + kk * NCOL);
                    unsigned long long w0 = dup2(w.x), w1 = dup2(w.y);
                    unsigned long long w2 = dup2(w.z), w3 = dup2(w.w);
                    fma2(acc[0][0], A0.x, w0); fma2(acc[0][1], A0.y, w0);
                    fma2(acc[0][2], A1.x, w0); fma2(acc[0][3], A1.y, w0);
                    fma2(acc[1][0], A0.x, w1); fma2(acc[1][1], A0.y, w1);
                    fma2(acc[1][2], A1.x, w1); fma2(acc[1][3], A1.y, w1);
                    fma2(acc[2][0], A0.x, w2); fma2(acc[2][1], A0.y, w2);
                    fma2(acc[2][2], A1.x, w2); fma2(acc[2][3], A1.y, w2);
                    fma2(acc[3][0], A0.x, w3); fma2(acc[3][1], A0.y, w3);
                    fma2(acc[3][2], A1.x, w3); fma2(acc[3][3], A1.y, w3);
                }
                __syncthreads();   // all reads of this buffer done
            }
        }

        if (act) {
            // split-K partials -> smem: red[kt][n][pair ^ ((n>>2)&3)]
            unsigned long long* red = (unsigned long long*)aS;
            #pragma unroll
            for (int c2 = 0; c2 < 4; c2++)
                #pragma unroll
                for (int j = 0; j < 4; j++)
                    red[kt * 1024 + (cbase + c2) * 32 +
                        ((bgroup * 4 + j) ^ wkey)] = acc[c2][j];
            __syncthreads();

            float4 s = make_float4(0.f, 0.f, 0.f, 0.f);
            #pragma unroll
            for (int q = 0; q < 8; q++) {
                float4 pz = *(const float4*)&aS[q * 2048 + en * 64 + fidx];
                s.x += pz.x; s.y += pz.y; s.z += pz.z; s.w += pz.w;
            }
            if (ckey & 1) s = make_float4(s.z, s.w, s.x, s.y);  // unswizzle

            const size_t vo = ((size_t)t * H + n0 + en) * B + eb;
            if (role == 1) {
                float4 o = make_float4(s.x + b1v, s.y + b1v, s.z + b1v, s.w + b1v);
                *(float4*)&g_pin[(size_t)(t & 1) * HB + (size_t)(n0 + en) * B + eb] = o;
            } else {
                float4 add;
                if (role == 0)
                    add = *(const float4*)&g_xin0[vo];
                else
                    add = __ldcg((const float4*)&g_pin[(size_t)(t & 1) * HB +
                                                       (size_t)(n0 + en) * B + eb]);
                v[0] = OMA * v[0] + AL * (s.x + add.x);
                v[1] = OMA * v[1] + AL * (s.y + add.y);
                v[2] = OMA * v[2] + AL * (s.z + add.z);
                v[3] = OMA * v[3] + AL * (s.w + add.w);
                float4 f = make_float4(fmaxf(v[0], 0.f), fmaxf(v[1], 0.f),
                                       fmaxf(v[2], 0.f), fmaxf(v[3], 0.f));
                float* dst = (role == 0) ? g_s0f : g_s1f;
                *(float4*)&dst[vo] = f;
            }
        }
        if (p < T + 1) gridbar();
    }
}

// ---------------------------------------------------------------------------
// transpose: [t][h][b] -> [b][t][h] for both layers.  grid (T, H/64, 2)
// ---------------------------------------------------------------------------
__global__ void __launch_bounds__(256)
transpose_kernel(float* __restrict__ st0, float* __restrict__ st1)
{
    __shared__ float tile[64][65];
    const int t  = blockIdx.x;
    const int h0 = blockIdx.y * 64;
    const float* src = blockIdx.z ? g_s1f : g_s0f;
    float* dst       = blockIdx.z ? st1 : st0;
    const int tid = threadIdx.x;
    #pragma unroll
    for (int i = tid; i < 64 * 64; i += 256) {
        int h = i >> 6, b = i & 63;
        tile[h][b] = src[((size_t)t * H + h0 + h) * B + b];
    }
    __syncthreads();
    #pragma unroll
    for (int i = tid; i < 64 * 64; i += 256) {
        int b = i >> 6, h = i & 63;
        dst[((size_t)b * T + t) * H + h0 + h] = tile[h][b];
    }
}

// ---------------------------------------------------------------------------
// gemm_in0: per timestep t, xin0[t][h][b] = W_in0[h,:] . x[b,t,:] + b0[h]
// ---------------------------------------------------------------------------
__global__ void __launch_bounds__(256)
gemm_in0_kernel(const float* __restrict__ x,
                const float* __restrict__ Win0,
                const float* __restrict__ b0)
{
    __shared__ float aS[16 * 64];
    __shared__ float bS[16 * 64];
    const int tid = threadIdx.x;
    const int m0 = blockIdx.x * 64;
    const int t  = blockIdx.y;
    const int lr = tid >> 2;
    const int lk = (tid & 3) * 4;
    const int tm4 = (tid >> 4) * 4;
    const int tn4 = (tid & 15) * 4;
    float acc[4][4] = {};
    const float* ap = Win0 + (size_t)(m0 + lr) * DIN + lk;
    const float* bp = x + ((size_t)lr * T + t) * DIN + lk;

    for (int k0 = 0; k0 < DIN; k0 += 16) {
        float4 av = *(const float4*)(ap + k0);
        float4 bv = *(const float4*)(bp + k0);
        __syncthreads();
        aS[(lk + 0) * 64 + lr] = av.x; aS[(lk + 1) * 64 + lr] = av.y;
        aS[(lk + 2) * 64 + lr] = av.z; aS[(lk + 3) * 64 + lr] = av.w;
        bS[(lk + 0) * 64 + lr] = bv.x; bS[(lk + 1) * 64 + lr] = bv.y;
        bS[(lk + 2) * 64 + lr] = bv.z; bS[(lk + 3) * 64 + lr] = bv.w;
        __syncthreads();
        #pragma unroll
        for (int kk = 0; kk < 16; kk++) {
            float4 a = *(const float4*)&aS[kk * 64 + tm4];
            float4 b = *(const float4*)&bS[kk * 64 + tn4];
            acc[0][0] += a.x * b.x; acc[0][1] += a.x * b.y;
            acc[0][2] += a.x * b.z; acc[0][3] += a.x * b.w;
            acc[1][0] += a.y * b.x; acc[1][1] += a.y * b.y;
            acc[1][2] += a.y * b.z; acc[1][3] += a.y * b.w;
            acc[2][0] += a.z * b.x; acc[2][1] += a.z * b.y;
            acc[2][2] += a.z * b.z; acc[2][3] += a.z * b.w;
            acc[3][0] += a.w * b.x; acc[3][1] += a.w * b.y;
            acc[3][2] += a.w * b.z; acc[3][3] += a.w * b.w;
        }
    }
    #pragma unroll
    for (int i = 0; i < 4; i++) {
        float bb = b0[m0 + tm4 + i];
        float4 o = make_float4(acc[i][0] + bb, acc[i][1] + bb,
                               acc[i][2] + bb, acc[i][3] + bb);
        *(float4*)&g_xin0[((size_t)t * H + m0 + tm4 + i) * B + tn4] = o;
    }
}

// ---------------------------------------------------------------------------
// gemm_out: output[B*T, DOUT] = states1[B*T, H] @ W_out^T + b_out
// ---------------------------------------------------------------------------
__global__ void __launch_bounds__(256)
gemm_out_kernel(const float* __restrict__ states1,
                const float* __restrict__ Wout,
                const float* __restrict__ bout,
                float* __restrict__ out)
{
    __shared__ float aS[16 * 64];
    __shared__ float bS[16 * 64];
    const int tid = threadIdx.x;
    const int m0 = blockIdx.x * 64;
    const int n0 = blockIdx.y * 64;
    const int lr = tid >> 2;
    const int lk = (tid & 3) * 4;
    const int tm4 = (tid >> 4) * 4;
    const int tn4 = (tid & 15) * 4;
    float acc[4][4] = {};
    const float* ap = states1 + (size_t)(m0 + lr) * H + lk;
    const float* bp = Wout    + (size_t)(n0 + lr) * H + lk;

    for (int k0 = 0; k0 < H; k0 += 16) {
        float4 av = *(const float4*)(ap + k0);
        float4 bv = *(const float4*)(bp + k0);
        __syncthreads();
        aS[(lk + 0) * 64 + lr] = av.x; aS[(lk + 1) * 64 + lr] = av.y;
        aS[(lk + 2) * 64 + lr] = av.z; aS[(lk + 3) * 64 + lr] = av.w;
        bS[(lk + 0) * 64 + lr] = bv.x; bS[(lk + 1) * 64 + lr] = bv.y;
        bS[(lk + 2) * 64 + lr] = bv.z; bS[(lk + 3) * 64 + lr] = bv.w;
        __syncthreads();
        #pragma unroll
        for (int kk = 0; kk < 16; kk++) {
            float4 a = *(const float4*)&aS[kk * 64 + tm4];
            float4 b = *(const float4*)&bS[kk * 64 + tn4];
            acc[0][0] += a.x * b.x; acc[0][1] += a.x * b.y;
            acc[0][2] += a.x * b.z; acc[0][3] += a.x * b.w;
            acc[1][0] += a.y * b.x; acc[1][1] += a.y * b.y;
            acc[1][2] += a.y * b.z; acc[1][3] += a.y * b.w;
            acc[2][0] += a.z * b.x; acc[2][1] += a.z * b.y;
            acc[2][2] += a.z * b.z; acc[2][3] += a.z * b.w;
            acc[3][0] += a.w * b.x; acc[3][1] += a.w * b.y;
            acc[3][2] += a.w * b.z; acc[3][3] += a.w * b.w;
        }
    }
    #pragma unroll
    for (int i = 0; i < 4; i++) {
        float4 bb = *(const float4*)&bout[n0 + tn4];
        int gm = m0 + tm4 + i;
        float4 o = make_float4(acc[i][0] + bb.x, acc[i][1] + bb.y,
                               acc[i][2] + bb.z, acc[i][3] + bb.w);
        *(float4*)&out[(size_t)gm * DOUT + n0 + tn4] = o;
    }
}

// ---------------------------------------------------------------------------
extern "C" void kernel_launch(void* const* d_in, const int* in_sizes, int n_in,
                              void* d_out, int out_size)
{
    (void)in_sizes; (void)n_in; (void)out_size;
    const float* x     = (const float*)d_in[0];
    const float* Win0  = (const float*)d_in[1];
    const float* Wrec0 = (const float*)d_in[2];
    const float* b0    = (const float*)d_in[3];
    const float* Win1  = (const float*)d_in[4];
    const float* Wrec1 = (const float*)d_in[5];
    const float* b1    = (const float*)d_in[6];
    const float* Wout  = (const float*)d_in[7];
    const float* bout  = (const float*)d_in[8];

    float* out     = (float*)d_out;                   // [B][T][DOUT]
    float* states0 = out + (size_t)B * T * DOUT;      // [B][T][H]
    float* states1 = states0 + (size_t)B * T * H;     // [B][T][H]

    cudaFuncSetAttribute(rnn_persistent,
                         cudaFuncAttributeMaxDynamicSharedMemorySize, SMEM_P);

    gemm_in0_kernel<<<dim3(H / 64, T), 256>>>(x, Win0, b0);
    rnn_persistent<<<NBLK, THR, SMEM_P>>>(Wrec0, Win1, Wrec1, b1);
    transpose_kernel<<<dim3(T, H / 64, 2), 256>>>(states0, states1);
    gemm_out_kernel<<<dim3((B * T) / 64, DOUT / 64), 256>>>(states1, Wout,
                                                            bout, out);
}

// round 7
// speedup vs baseline: 1.6259x; 1.0001x over previous
#include <cuda_runtime.h>

// ---------------------------------------------------------------------------
// Leaky CTRNN persistent scan, v4. B=64, T=512, D_IN=256, H=1024, D_OUT=256
//
//  k1: gemm_in0 — xin0[t][h][b] = W_in0 @ x[:,t,:]^T + b0
//  k2: rnn_persistent — 96 blocks x 512 thr (1/SM, co-resident), 514 phases:
//       role0 (blk  0-31): fr0(p)   = relu(v0=.9v0+.1(fr0(p-1)@Wrec0^T + xin0))
//       role1 (blk 32-63): pin(p-1) = fr0(p-1)@Win1^T + b1
//       role2 (blk 64-95): fr1(p-2) = relu(v1=.9v1+.1(fr1(p-3)@Wrec1^T + pin))
//      Weights persist in smem. A staged per 128-k chunk via cp.async.bulk
//      (TMA) + mbarrier, double-buffered (no per-thread LDGSTS cost).
//      Split-K x8, microtile 8 batches x 4 cols / thread, fma.rn.f32x2.
//      Swizzled smem reduce (2-way STS instead of 8-way).
//  k3: transpose — [t][h][b] -> states[b][t][h]
//  k4: gemm_out — output = states1 @ W_out^T + b_out
// ---------------------------------------------------------------------------

namespace {
constexpr int B = 64, T = 512, DIN = 256, H = 1024, DOUT = 256;
constexpr float AL = 0.1f, OMA = 0.9f;

constexpr int NBLK = 96;
constexpr int THR  = 512;
constexpr int NCOL = 32;             // weight cols per block
constexpr int KC   = 128;            // k-chunk staged in smem
constexpr int NCH  = H / KC;         // 8
constexpr int HB   = H * B;
constexpr int ABUF = 2 * KC * B;     // floats (64KB), reused for reduce
constexpr int CBYTES = KC * B * 4;   // 32768 bytes per chunk
constexpr int MBAR_OFF = (ABUF + H * NCOL) * 4;     // byte offset of mbarriers
constexpr int SMEM_P   = MBAR_OFF + 16;             // + two 8B mbarriers
}

// Scratch (__device__ globals: allocation-free rule)
__device__ float g_xin0[(size_t)T * H * B];   // [t][h][b]
__device__ float g_s0f[(size_t)T * H * B];    // fr0 history [t][h][b]
__device__ float g_s1f[(size_t)T * H * B];    // fr1 history [t][h][b]
__device__ float g_pin[2 * (size_t)H * B];    // [t&1][h][b]
__device__ volatile unsigned g_gen;
__device__ unsigned g_cnt;

// ---- helpers ---------------------------------------------------------------
__device__ __forceinline__ unsigned long long dup2(float x) {
    unsigned long long d;
    asm("mov.b64 %0, {%1, %1};" : "=l"(d) : "r"(__float_as_uint(x)));
    return d;
}
__device__ __forceinline__ void fma2(unsigned long long& a,
                                     unsigned long long x, unsigned long long y) {
    asm("fma.rn.f32x2 %0, %1, %2, %0;" : "+l"(a) : "l"(x), "l"(y));
}
__device__ __forceinline__ void mbar_init(unsigned mbar, unsigned count) {
    asm volatile("mbarrier.init.shared.b64 [%0], %1;" :: "r"(mbar), "r"(count)
                 : "memory");
}
__device__ __forceinline__ void mbar_expect_tx(unsigned mbar, unsigned bytes) {
    asm volatile("mbarrier.arrive.expect_tx.shared.b64 _, [%0], %1;"
                 :: "r"(mbar), "r"(bytes) : "memory");
}
__device__ __forceinline__ void bulk_g2s(unsigned dst, const float* src,
                                         unsigned bytes, unsigned mbar) {
    asm volatile(
        "cp.async.bulk.shared::cta.global.mbarrier::complete_tx::bytes "
        "[%0], [%1], %2, [%3];"
        :: "r"(dst), "l"(src), "r"(bytes), "r"(mbar) : "memory");
}
__device__ __forceinline__ void mbar_wait(unsigned mbar, unsigned parity) {
    asm volatile(
        "{\n\t"
        ".reg .pred P;\n\t"
        "LAB_%=:\n\t"
        "mbarrier.try_wait.parity.shared.b64 P, [%0], %1;\n\t"
        "@!P bra LAB_%=;\n\t"
        "}\n"
        :: "r"(mbar), "r"(parity) : "memory");
}

__device__ __forceinline__ void gridbar() {
    __syncthreads();
    if (threadIdx.x == 0) {
        __threadfence();
        unsigned gen = g_gen;
        if (atomicAdd(&g_cnt, 1u) == NBLK - 1) {
            g_cnt = 0;
            __threadfence();
            g_gen = gen + 1;
        } else {
            while (g_gen == gen) { __nanosleep(64); }
            __threadfence();
        }
    }
    __syncthreads();
}

// ---------------------------------------------------------------------------
__global__ void __launch_bounds__(THR, 1)
rnn_persistent(const float* __restrict__ Wrec0, const float* __restrict__ Win1,
               const float* __restrict__ Wrec1, const float* __restrict__ b1)
{
    extern __shared__ float sm[];
    float* aS = sm;                  // [2][KC][B], reused as reduce scratch
    float* wS = sm + ABUF;           // [H][NCOL] k-major

    const unsigned sbase = (unsigned)__cvta_generic_to_shared(sm);
    const unsigned mb0 = sbase + MBAR_OFF;
    const unsigned mb1 = sbase + MBAR_OFF + 8;
    const unsigned abuf0 = sbase;
    const unsigned abuf1 = sbase + CBYTES;

    const int tid  = threadIdx.x;
    const int role = (int)blockIdx.x >> 5;
    const int n0   = ((int)blockIdx.x & 31) * NCOL;

    // split-K slice / microtile mapping (conflict-free LDS)
    const int kt     = tid >> 6;         // k-slice 0..7
    const int tl     = tid & 63;
    const int bgroup = tl & 7;           // 8 batches -> bbase = bgroup*8
    const int cgroup = tl >> 3;          // 4 cols    -> cbase = cgroup*4
    const int bbase  = bgroup * 8;
    const int cbase  = cgroup * 4;
    const int wkey   = cgroup & 3;       // reduce swizzle key (= (n>>2)&3)

    // One-time weight load: wS[k][n] = W[n0+n][k]
    const float* Wsrc = role == 0 ? Wrec0 : (role == 1 ? Win1 : Wrec1);
    for (int it = tid; it < NCOL * (H / 4); it += THR) {
        int n = it & 31, k4 = (it >> 5) << 2;
        float4 w = *(const float4*)(Wsrc + (size_t)(n0 + n) * H + k4);
        wS[(k4 + 0) * NCOL + n] = w.x; wS[(k4 + 1) * NCOL + n] = w.y;
        wS[(k4 + 2) * NCOL + n] = w.z; wS[(k4 + 3) * NCOL + n] = w.w;
    }
    // epilogue mapping: 4 contiguous batch outputs of one col per thread
    const int en = tid >> 4;             // local col 0..31
    const int eb = (tid & 15) * 4;       // batch 0..60
    const int ckey = (en >> 2) & 3;      // reader swizzle key
    const int prbase = (tid & 15) * 2;   // batch-pair base (even)
    const int fidx = ((prbase ^ ckey) & ~1) * 2;  // float idx of float4 slot
    const float b1v = (role == 1) ? b1[n0 + en] : 0.f;

    if (tid == 0) { mbar_init(mb0, 1); mbar_init(mb1, 1); }
    asm volatile("fence.proxy.async.shared::cta;" ::: "memory");
    __syncthreads();

    unsigned par0 = 0, par1 = 0;
    float v[4] = {0.f, 0.f, 0.f, 0.f};

    for (int p = 0; p < T + 2; p++) {
        int t; const float* asrc = nullptr; bool act, dogemm;
        if (role == 0) {
            t = p; act = (t < T); dogemm = act && (p > 0);
            if (dogemm) asrc = g_s0f + (size_t)(p - 1) * HB;
        } else if (role == 1) {
            t = p - 1; act = (t >= 0 && t < T); dogemm = act;
            if (dogemm) asrc = g_s0f + (size_t)t * HB;
        } else {
            t = p - 2; act = (t >= 0 && t < T); dogemm = act && (t > 0);
            if (dogemm) asrc = g_s1f + (size_t)(t - 1) * HB;
        }

        // acc[col 0..3][batch-pair 0..3]
        unsigned long long acc[4][4];
        #pragma unroll
        for (int c2 = 0; c2 < 4; c2++)
            #pragma unroll
            for (int j = 0; j < 4; j++) acc[c2][j] = 0ull;

        if (dogemm) {
            if (tid == 0) {                       // prefetch chunk 0
                mbar_expect_tx(mb0, CBYTES);
                bulk_g2s(abuf0, asrc, CBYTES, mb0);
            }
            for (int c = 0; c < NCH; c++) {
                if (c + 1 < NCH && tid == 0) {    // prefetch chunk c+1
                    unsigned dst = ((c + 1) & 1) ? abuf1 : abuf0;
                    unsigned mbn = ((c + 1) & 1) ? mb1 : mb0;
                    mbar_expect_tx(mbn, CBYTES);
                    bulk_g2s(dst, asrc + (size_t)(c + 1) * KC * B, CBYTES, mbn);
                }
                if (c & 1) { mbar_wait(mb1, par1); par1 ^= 1; }
                else       { mbar_wait(mb0, par0); par0 ^= 1; }

                const float* ab = aS + (c & 1) * (KC * B) + (kt * 16) * B + bbase;
                const float* wb = wS + (c * KC + kt * 16) * NCOL + cbase;
                #pragma unroll
                for (int kk = 0; kk < 16; kk++) {
                    ulonglong2 A0 = *(const ulonglong2*)(ab + kk * B);      // b..b+3
                    ulonglong2 A1 = *(const ulonglong2*)(ab + kk * B + 4);  // b+4..b+7
                    float4 w = *(const float4*)(wb + kk * NCOL);
                    unsigned long long w0 = dup2(w.x), w1 = dup2(w.y);
                    unsigned long long w2 = dup2(w.z), w3 = dup2(w.w);
                    fma2(acc[0][0], A0.x, w0); fma2(acc[0][1], A0.y, w0);
                    fma2(acc[0][2], A1.x, w0); fma2(acc[0][3], A1.y, w0);
                    fma2(acc[1][0], A0.x, w1); fma2(acc[1][1], A0.y, w1);
                    fma2(acc[1][2], A1.x, w1); fma2(acc[1][3], A1.y, w1);
                    fma2(acc[2][0], A0.x, w2); fma2(acc[2][1], A0.y, w2);
                    fma2(acc[2][2], A1.x, w2); fma2(acc[2][3], A1.y, w2);
                    fma2(acc[3][0], A0.x, w3); fma2(acc[3][1], A0.y, w3);
                    fma2(acc[3][2], A1.x, w3); fma2(acc[3][3], A1.y, w3);
                }
                __syncthreads();   // all reads of this buffer done
            }
        }

        if (act) {
            // split-K partials -> smem: red[kt][n][pair ^ ((n>>2)&3)]
            unsigned long long* red = (unsigned long long*)aS;
            #pragma unroll
            for (int c2 = 0; c2 < 4; c2++)
                #pragma unroll
                for (int j = 0; j < 4; j++)
                    red[kt * 1024 + (cbase + c2) * 32 +
                        ((bgroup * 4 + j) ^ wkey)] = acc[c2][j];
            __syncthreads();

            float4 s = make_float4(0.f, 0.f, 0.f, 0.f);
            #pragma unroll
            for (int q = 0; q < 8; q++) {
                float4 pz = *(const float4*)&aS[q * 2048 + en * 64 + fidx];
                s.x += pz.x; s.y += pz.y; s.z += pz.z; s.w += pz.w;
            }
            if (ckey & 1) s = make_float4(s.z, s.w, s.x, s.y);  // unswizzle

            const size_t vo = ((size_t)t * H + n0 + en) * B + eb;
            if (role == 1) {
                float4 o = make_float4(s.x + b1v, s.y + b1v, s.z + b1v, s.w + b1v);
                *(float4*)&g_pin[(size_t)(t & 1) * HB + (size_t)(n0 + en) * B + eb] = o;
            } else {
                float4 add;
                if (role == 0)
                    add = *(const float4*)&g_xin0[vo];
                else
                    add = __ldcg((const float4*)&g_pin[(size_t)(t & 1) * HB +
                                                       (size_t)(n0 + en) * B + eb]);
                v[0] = OMA * v[0] + AL * (s.x + add.x);
                v[1] = OMA * v[1] + AL * (s.y + add.y);
                v[2] = OMA * v[2] + AL * (s.z + add.z);
                v[3] = OMA * v[3] + AL * (s.w + add.w);
                float4 f = make_float4(fmaxf(v[0], 0.f), fmaxf(v[1], 0.f),
                                       fmaxf(v[2], 0.f), fmaxf(v[3], 0.f));
                float* dst = (role == 0) ? g_s0f : g_s1f;
                *(float4*)&dst[vo] = f;
            }
        }
        if (p < T + 1) gridbar();
    }
}

// ---------------------------------------------------------------------------
// transpose: [t][h][b] -> [b][t][h] for both layers.  grid (T, H/64, 2)
// ---------------------------------------------------------------------------
__global__ void __launch_bounds__(256)
transpose_kernel(float* __restrict__ st0, float* __restrict__ st1)
{
    __shared__ float tile[64][65];
    const int t  = blockIdx.x;
    const int h0 = blockIdx.y * 64;
    const float* src = blockIdx.z ? g_s1f : g_s0f;
    float* dst       = blockIdx.z ? st1 : st0;
    const int tid = threadIdx.x;
    #pragma unroll
    for (int i = tid; i < 64 * 64; i += 256) {
        int h = i >> 6, b = i & 63;
        tile[h][b] = src[((size_t)t * H + h0 + h) * B + b];
    }
    __syncthreads();
    #pragma unroll
    for (int i = tid; i < 64 * 64; i += 256) {
        int b = i >> 6, h = i & 63;
        dst[((size_t)b * T + t) * H + h0 + h] = tile[h][b];
    }
}

// ---------------------------------------------------------------------------
// gemm_in0: per timestep t, xin0[t][h][b] = W_in0[h,:] . x[b,t,:] + b0[h]
// ---------------------------------------------------------------------------
__global__ void __launch_bounds__(256)
gemm_in0_kernel(const float* __restrict__ x,
                const float* __restrict__ Win0,
                const float* __restrict__ b0)
{
    __shared__ float aS[16 * 64];
    __shared__ float bS[16 * 64];
    const int tid = threadIdx.x;
    const int m0 = blockIdx.x * 64;
    const int t  = blockIdx.y;
    const int lr = tid >> 2;
    const int lk = (tid & 3) * 4;
    const int tm4 = (tid >> 4) * 4;
    const int tn4 = (tid & 15) * 4;
    float acc[4][4] = {};
    const float* ap = Win0 + (size_t)(m0 + lr) * DIN + lk;
    const float* bp = x + ((size_t)lr * T + t) * DIN + lk;

    for (int k0 = 0; k0 < DIN; k0 += 16) {
        float4 av = *(const float4*)(ap + k0);
        float4 bv = *(const float4*)(bp + k0);
        __syncthreads();
        aS[(lk + 0) * 64 + lr] = av.x; aS[(lk + 1) * 64 + lr] = av.y;
        aS[(lk + 2) * 64 + lr] = av.z; aS[(lk + 3) * 64 + lr] = av.w;
        bS[(lk + 0) * 64 + lr] = bv.x; bS[(lk + 1) * 64 + lr] = bv.y;
        bS[(lk + 2) * 64 + lr] = bv.z; bS[(lk + 3) * 64 + lr] = bv.w;
        __syncthreads();
        #pragma unroll
        for (int kk = 0; kk < 16; kk++) {
            float4 a = *(const float4*)&aS[kk * 64 + tm4];
            float4 b = *(const float4*)&bS[kk * 64 + tn4];
            acc[0][0] += a.x * b.x; acc[0][1] += a.x * b.y;
            acc[0][2] += a.x * b.z; acc[0][3] += a.x * b.w;
            acc[1][0] += a.y * b.x; acc[1][1] += a.y * b.y;
            acc[1][2] += a.y * b.z; acc[1][3] += a.y * b.w;
            acc[2][0] += a.z * b.x; acc[2][1] += a.z * b.y;
            acc[2][2] += a.z * b.z; acc[2][3] += a.z * b.w;
            acc[3][0] += a.w * b.x; acc[3][1] += a.w * b.y;
            acc[3][2] += a.w * b.z; acc[3][3] += a.w * b.w;
        }
    }
    #pragma unroll
    for (int i = 0; i < 4; i++) {
        float bb = b0[m0 + tm4 + i];
        float4 o = make_float4(acc[i][0] + bb, acc[i][1] + bb,
                               acc[i][2] + bb, acc[i][3] + bb);
        *(float4*)&g_xin0[((size_t)t * H + m0 + tm4 + i) * B + tn4] = o;
    }
}

// ---------------------------------------------------------------------------
// gemm_out: output[B*T, DOUT] = states1[B*T, H] @ W_out^T + b_out
// ---------------------------------------------------------------------------
__global__ void __launch_bounds__(256)
gemm_out_kernel(const float* __restrict__ states1,
                const float* __restrict__ Wout,
                const float* __restrict__ bout,
                float* __restrict__ out)
{
    __shared__ float aS[16 * 64];
    __shared__ float bS[16 * 64];
    const int tid = threadIdx.x;
    const int m0 = blockIdx.x * 64;
    const int n0 = blockIdx.y * 64;
    const int lr = tid >> 2;
    const int lk = (tid & 3) * 4;
    const int tm4 = (tid >> 4) * 4;
    const int tn4 = (tid & 15) * 4;
    float acc[4][4] = {};
    const float* ap = states1 + (size_t)(m0 + lr) * H + lk;
    const float* bp = Wout    + (size_t)(n0 + lr) * H + lk;

    for (int k0 = 0; k0 < H; k0 += 16) {
        float4 av = *(const float4*)(ap + k0);
        float4 bv = *(const float4*)(bp + k0);
        __syncthreads();
        aS[(lk + 0) * 64 + lr] = av.x; aS[(lk + 1) * 64 + lr] = av.y;
        aS[(lk + 2) * 64 + lr] = av.z; aS[(lk + 3) * 64 + lr] = av.w;
        bS[(lk + 0) * 64 + lr] = bv.x; bS[(lk + 1) * 64 + lr] = bv.y;
        bS[(lk + 2) * 64 + lr] = bv.z; bS[(lk + 3) * 64 + lr] = bv.w;
        __syncthreads();
        #pragma unroll
        for (int kk = 0; kk < 16; kk++) {
            float4 a = *(const float4*)&aS[kk * 64 + tm4];
            float4 b = *(const float4*)&bS[kk * 64 + tn4];
            acc[0][0] += a.x * b.x; acc[0][1] += a.x * b.y;
            acc[0][2] += a.x * b.z; acc[0][3] += a.x * b.w;
            acc[1][0] += a.y * b.x; acc[1][1] += a.y * b.y;
            acc[1][2] += a.y * b.z; acc[1][3] += a.y * b.w;
            acc[2][0] += a.z * b.x; acc[2][1] += a.z * b.y;
            acc[2][2] += a.z * b.z; acc[2][3] += a.z * b.w;
            acc[3][0] += a.w * b.x; acc[3][1] += a.w * b.y;
            acc[3][2] += a.w * b.z; acc[3][3] += a.w * b.w;
        }
    }
    #pragma unroll
    for (int i = 0; i < 4; i++) {
        float4 bb = *(const float4*)&bout[n0 + tn4];
        int gm = m0 + tm4 + i;
        float4 o = make_float4(acc[i][0] + bb.x, acc[i][1] + bb.y,
                               acc[i][2] + bb.z, acc[i][3] + bb.w);
        *(float4*)&out[(size_t)gm * DOUT + n0 + tn4] = o;
    }
}

// ---------------------------------------------------------------------------
extern "C" void kernel_launch(void* const* d_in, const int* in_sizes, int n_in,
                              void* d_out, int out_size)
{
    (void)in_sizes; (void)n_in; (void)out_size;
    const float* x     = (const float*)d_in[0];
    const float* Win0  = (const float*)d_in[1];
    const float* Wrec0 = (const float*)d_in[2];
    const float* b0    = (const float*)d_in[3];
    const float* Win1  = (const float*)d_in[4];
    const float* Wrec1 = (const float*)d_in[5];
    const float* b1    = (const float*)d_in[6];
    const float* Wout  = (const float*)d_in[7];
    const float* bout  = (const float*)d_in[8];

    float* out     = (float*)d_out;                   // [B][T][DOUT]
    float* states0 = out + (size_t)B * T * DOUT;      // [B][T][H]
    float* states1 = states0 + (size_t)B * T * H;     // [B][T][H]

    cudaFuncSetAttribute(rnn_persistent,
                         cudaFuncAttributeMaxDynamicSharedMemorySize, SMEM_P);

    gemm_in0_kernel<<<dim3(H / 64, T), 256>>>(x, Win0, b0);
    rnn_persistent<<<NBLK, THR, SMEM_P>>>(Wrec0, Win1, Wrec1, b1);
    transpose_kernel<<<dim3(T, H / 64, 2), 256>>>(states0, states1);
    gemm_out_kernel<<<dim3((B * T) / 64, DOUT / 64), 256>>>(states1, Wout,
                                                            bout, out);
}